// round 1
// baseline (speedup 1.0000x reference)
#include <cuda_runtime.h>
#include <math.h>

#define F 256
#define NN 4096
#define TT 8

// ---------------- scratch (no allocations allowed) ----------------
__device__ float g_sn[2];
__device__ float g_Q[2 * 2 * F * F];   // [layer][pingpong][F*F]
__device__ float g_zt[F * F];
__device__ float g_upd[F * F];
__device__ float g_rst[F * F];
__device__ float g_whz[F * F];
__device__ float g_Y[NN * F];
__device__ float g_h1[NN * F];

// ---------------- scorer norms ----------------
__global__ void __launch_bounds__(256) sn_kernel(const float* __restrict__ s0,
                                                 const float* __restrict__ s1) {
    const float* s = (blockIdx.x == 0) ? s0 : s1;
    float p = s[threadIdx.x];
    p = p * p;
#pragma unroll
    for (int o = 16; o > 0; o >>= 1) p += __shfl_xor_sync(0xffffffffu, p, o);
    __shared__ float ws[8];
    if ((threadIdx.x & 31) == 0) ws[threadIdx.x >> 5] = p;
    __syncthreads();
    if (threadIdx.x == 0) {
        float sum = 0.f;
#pragma unroll
        for (int i = 0; i < 8; i++) sum += ws[i];
        g_sn[blockIdx.x] = sqrtf(sum);
    }
}

// ---------------- zt = (embs * tanh(embs@scorer / sn))[:256].T ----------------
// one block per node n (n < 256), 256 threads over features
__global__ void __launch_bounds__(256) zt_kernel(const float* __restrict__ embs,
                                                 const float* __restrict__ scorer,
                                                 int layer, float* __restrict__ ztout) {
    const int n = blockIdx.x;
    const int f = threadIdx.x;
    float v = embs[n * F + f];
    float p = v * scorer[f];
#pragma unroll
    for (int o = 16; o > 0; o >>= 1) p += __shfl_xor_sync(0xffffffffu, p, o);
    __shared__ float ws[8];
    __shared__ float tval;
    if ((f & 31) == 0) ws[f >> 5] = p;
    __syncthreads();
    if (f == 0) {
        float s = 0.f;
#pragma unroll
        for (int i = 0; i < 8; i++) s += ws[i];
        tval = tanhf(s / g_sn[layer]);
    }
    __syncthreads();
    ztout[f * F + n] = v * tval;
}

// ---------------- generic SGEMM: C = [relu](A @ B), row-major ----------------
// block tile 128(M) x 64(N), K-tile 16, 256 threads, 8x4 per thread
__global__ void __launch_bounds__(256) sgemm_kernel(const float* __restrict__ A,
                                                    const float* __restrict__ B,
                                                    float* __restrict__ C,
                                                    int M, int N, int K, int do_relu) {
    __shared__ float As[16][128];
    __shared__ float Bs[16][64];
    const int bm = blockIdx.y * 128;
    const int bn = blockIdx.x * 64;
    const int tid = threadIdx.x;
    const int tx = tid & 15;
    const int ty = tid >> 4;

    float acc[8][4];
#pragma unroll
    for (int i = 0; i < 8; i++)
#pragma unroll
        for (int j = 0; j < 4; j++) acc[i][j] = 0.f;

    const int arow0 = tid >> 2;        // 0..63
    const int akk   = (tid & 3) << 2;  // 0,4,8,12
    const int brow  = tid >> 4;        // 0..15
    const int bnn   = (tid & 15) << 2; // 0..60

    for (int k0 = 0; k0 < K; k0 += 16) {
#pragma unroll
        for (int i = 0; i < 2; i++) {
            const int row = arow0 + i * 64;
            float4 v = *(const float4*)(A + (size_t)(bm + row) * K + (k0 + akk));
            As[akk + 0][row] = v.x;
            As[akk + 1][row] = v.y;
            As[akk + 2][row] = v.z;
            As[akk + 3][row] = v.w;
        }
        {
            float4 v = *(const float4*)(B + (size_t)(k0 + brow) * N + (bn + bnn));
            *(float4*)(&Bs[brow][bnn]) = v;
        }
        __syncthreads();
#pragma unroll
        for (int k = 0; k < 16; k++) {
            float4 a0 = *(const float4*)(&As[k][ty * 8]);
            float4 a1 = *(const float4*)(&As[k][ty * 8 + 4]);
            float4 bv = *(const float4*)(&Bs[k][tx * 4]);
            float a[8] = {a0.x, a0.y, a0.z, a0.w, a1.x, a1.y, a1.z, a1.w};
            float b[4] = {bv.x, bv.y, bv.z, bv.w};
#pragma unroll
            for (int i = 0; i < 8; i++)
#pragma unroll
                for (int j = 0; j < 4; j++) acc[i][j] += a[i] * b[j];
        }
        __syncthreads();
    }
#pragma unroll
    for (int i = 0; i < 8; i++) {
        float4 v;
        v.x = acc[i][0]; v.y = acc[i][1]; v.z = acc[i][2]; v.w = acc[i][3];
        if (do_relu) {
            v.x = fmaxf(v.x, 0.f); v.y = fmaxf(v.y, 0.f);
            v.z = fmaxf(v.z, 0.f); v.w = fmaxf(v.w, 0.f);
        }
        *(float4*)(C + (size_t)(bm + ty * 8 + i) * N + bn + tx * 4) = v;
    }
}

// ---------------- GRU stage 1: upd=sig(Wz@zt+Uz@Q+bz), rst=sig(Wr@zt+Ur@Q+br), whz=Wh@zt+bh
// grid (4,4,3): z = gate; 64x64 tiles, 4x4 per thread
__global__ void __launch_bounds__(256) gru_stage1_kernel(
    const float* __restrict__ Wz, const float* __restrict__ Uz, const float* __restrict__ bz,
    const float* __restrict__ Wr, const float* __restrict__ Ur, const float* __restrict__ br,
    const float* __restrict__ Wh, const float* __restrict__ bh,
    const float* __restrict__ zt, const float* __restrict__ Q,
    float* __restrict__ upd, float* __restrict__ rst, float* __restrict__ whz) {
    const int gate = blockIdx.z;
    const float *A1, *A2, *bias;
    float* out;
    if (gate == 0)      { A1 = Wz; A2 = Uz; bias = bz; out = upd; }
    else if (gate == 1) { A1 = Wr; A2 = Ur; bias = br; out = rst; }
    else                { A1 = Wh; A2 = nullptr; bias = bh; out = whz; }

    __shared__ float A1s[16][64], B1s[16][64], A2s[16][64], B2s[16][64];
    const int bm = blockIdx.y * 64, bn = blockIdx.x * 64;
    const int tid = threadIdx.x, tx = tid & 15, ty = tid >> 4;
    const int arow = tid >> 2, akk = (tid & 3) << 2;
    const int brow = tid >> 4, bnn = (tid & 15) << 2;

    float acc[4][4];
#pragma unroll
    for (int i = 0; i < 4; i++)
#pragma unroll
        for (int j = 0; j < 4; j++) acc[i][j] = 0.f;

    for (int k0 = 0; k0 < F; k0 += 16) {
        {
            float4 v = *(const float4*)(A1 + (size_t)(bm + arow) * F + k0 + akk);
            A1s[akk + 0][arow] = v.x; A1s[akk + 1][arow] = v.y;
            A1s[akk + 2][arow] = v.z; A1s[akk + 3][arow] = v.w;
            float4 w = *(const float4*)(zt + (size_t)(k0 + brow) * F + bn + bnn);
            *(float4*)(&B1s[brow][bnn]) = w;
        }
        if (gate < 2) {
            float4 v = *(const float4*)(A2 + (size_t)(bm + arow) * F + k0 + akk);
            A2s[akk + 0][arow] = v.x; A2s[akk + 1][arow] = v.y;
            A2s[akk + 2][arow] = v.z; A2s[akk + 3][arow] = v.w;
            float4 w = *(const float4*)(Q + (size_t)(k0 + brow) * F + bn + bnn);
            *(float4*)(&B2s[brow][bnn]) = w;
        }
        __syncthreads();
        if (gate < 2) {
#pragma unroll
            for (int k = 0; k < 16; k++) {
                float4 a1 = *(const float4*)(&A1s[k][ty * 4]);
                float4 b1 = *(const float4*)(&B1s[k][tx * 4]);
                float4 a2 = *(const float4*)(&A2s[k][ty * 4]);
                float4 b2 = *(const float4*)(&B2s[k][tx * 4]);
                float av1[4] = {a1.x, a1.y, a1.z, a1.w};
                float bv1[4] = {b1.x, b1.y, b1.z, b1.w};
                float av2[4] = {a2.x, a2.y, a2.z, a2.w};
                float bv2[4] = {b2.x, b2.y, b2.z, b2.w};
#pragma unroll
                for (int i = 0; i < 4; i++)
#pragma unroll
                    for (int j = 0; j < 4; j++)
                        acc[i][j] += av1[i] * bv1[j] + av2[i] * bv2[j];
            }
        } else {
#pragma unroll
            for (int k = 0; k < 16; k++) {
                float4 a1 = *(const float4*)(&A1s[k][ty * 4]);
                float4 b1 = *(const float4*)(&B1s[k][tx * 4]);
                float av1[4] = {a1.x, a1.y, a1.z, a1.w};
                float bv1[4] = {b1.x, b1.y, b1.z, b1.w};
#pragma unroll
                for (int i = 0; i < 4; i++)
#pragma unroll
                    for (int j = 0; j < 4; j++) acc[i][j] += av1[i] * bv1[j];
            }
        }
        __syncthreads();
    }
#pragma unroll
    for (int i = 0; i < 4; i++)
#pragma unroll
        for (int j = 0; j < 4; j++) {
            const int gm = bm + ty * 4 + i;
            const int gn = bn + tx * 4 + j;
            float v = acc[i][j] + bias[gm * F + gn];
            if (gate < 2) v = 1.f / (1.f + expf(-v));
            out[gm * F + gn] = v;
        }
}

// ---------------- GRU stage 2: hcap = tanh(whz + Uh@(rst*Q)); Qn = (1-u)Q + u*hcap
__global__ void __launch_bounds__(256) gru_stage2_kernel(
    const float* __restrict__ Uh, const float* __restrict__ Q,
    const float* __restrict__ rst, const float* __restrict__ upd,
    const float* __restrict__ whz, float* __restrict__ Qn) {
    __shared__ float As[16][64], Bs[16][64];
    const int bm = blockIdx.y * 64, bn = blockIdx.x * 64;
    const int tid = threadIdx.x, tx = tid & 15, ty = tid >> 4;
    const int arow = tid >> 2, akk = (tid & 3) << 2;
    const int brow = tid >> 4, bnn = (tid & 15) << 2;

    float acc[4][4];
#pragma unroll
    for (int i = 0; i < 4; i++)
#pragma unroll
        for (int j = 0; j < 4; j++) acc[i][j] = 0.f;

    for (int k0 = 0; k0 < F; k0 += 16) {
        {
            float4 v = *(const float4*)(Uh + (size_t)(bm + arow) * F + k0 + akk);
            As[akk + 0][arow] = v.x; As[akk + 1][arow] = v.y;
            As[akk + 2][arow] = v.z; As[akk + 3][arow] = v.w;
            float4 r = *(const float4*)(rst + (size_t)(k0 + brow) * F + bn + bnn);
            float4 q = *(const float4*)(Q + (size_t)(k0 + brow) * F + bn + bnn);
            float4 w;
            w.x = r.x * q.x; w.y = r.y * q.y; w.z = r.z * q.z; w.w = r.w * q.w;
            *(float4*)(&Bs[brow][bnn]) = w;
        }
        __syncthreads();
#pragma unroll
        for (int k = 0; k < 16; k++) {
            float4 a = *(const float4*)(&As[k][ty * 4]);
            float4 b = *(const float4*)(&Bs[k][tx * 4]);
            float av[4] = {a.x, a.y, a.z, a.w};
            float bv[4] = {b.x, b.y, b.z, b.w};
#pragma unroll
            for (int i = 0; i < 4; i++)
#pragma unroll
                for (int j = 0; j < 4; j++) acc[i][j] += av[i] * bv[j];
        }
        __syncthreads();
    }
#pragma unroll
    for (int i = 0; i < 4; i++)
#pragma unroll
        for (int j = 0; j < 4; j++) {
            const int idx = (bm + ty * 4 + i) * F + bn + tx * 4 + j;
            float h = tanhf(acc[i][j] + whz[idx]);
            float u = upd[idx];
            Qn[idx] = (1.f - u) * Q[idx] + u * h;
        }
}

// ---------------- orchestration ----------------
extern "C" void kernel_launch(void* const* d_in, const int* in_sizes, int n_in,
                              void* d_out, int out_size) {
    const float* in[25];
    for (int i = 0; i < 25; i++) in[i] = (const float*)d_in[i];
    const float* A = in[0];
    const float* X = in[1];
    // 3: l0_scorer, 4..13: l0 Wz Uz bz Wr Ur br Wh Uh bh Q0
    // 14: l1_scorer, 15..24: l1 Wz Uz bz Wr Ur br Wh Uh bh Q0

    float *Qb, *zt, *upd, *rst, *whz, *Y, *h1;
    cudaGetSymbolAddress((void**)&Qb, g_Q);
    cudaGetSymbolAddress((void**)&zt, g_zt);
    cudaGetSymbolAddress((void**)&upd, g_upd);
    cudaGetSymbolAddress((void**)&rst, g_rst);
    cudaGetSymbolAddress((void**)&whz, g_whz);
    cudaGetSymbolAddress((void**)&Y, g_Y);
    cudaGetSymbolAddress((void**)&h1, g_h1);

    sn_kernel<<<2, 256>>>(in[3], in[14]);

    for (int t = 0; t < TT; t++) {
        const float* embs0 = X + (size_t)t * NN * F;
        const float* At = A + (size_t)t * NN * NN;

        // ---- layer 0 ----
        const float* q0in = (t == 0) ? in[13] : Qb + (size_t)(0 * 2 + ((t - 1) & 1)) * F * F;
        float* q0out = Qb + (size_t)(0 * 2 + (t & 1)) * F * F;
        zt_kernel<<<256, 256>>>(embs0, in[3], 0, zt);
        gru_stage1_kernel<<<dim3(4, 4, 3), 256>>>(in[4], in[5], in[6], in[7], in[8], in[9],
                                                  in[10], in[12], zt, q0in, upd, rst, whz);
        gru_stage2_kernel<<<dim3(4, 4), 256>>>(in[11], q0in, rst, upd, whz, q0out);
        // Y = embs0 @ Qn  [4096,256]
        sgemm_kernel<<<dim3(4, 32), 256>>>(embs0, q0out, Y, NN, F, F, 0);
        // h1 = relu(A[t] @ Y); for t<7 only the first 256 rows are ever consumed
        const int Mrows = (t == TT - 1) ? NN : F;
        sgemm_kernel<<<dim3(4, Mrows / 128), 256>>>(At, Y, h1, Mrows, F, NN, 1);

        // ---- layer 1 ----
        const float* q1in = (t == 0) ? in[24] : Qb + (size_t)(2 + ((t - 1) & 1)) * F * F;
        float* q1out = Qb + (size_t)(2 + (t & 1)) * F * F;
        zt_kernel<<<256, 256>>>(h1, in[14], 1, zt);
        gru_stage1_kernel<<<dim3(4, 4, 3), 256>>>(in[15], in[16], in[17], in[18], in[19],
                                                  in[20], in[21], in[23], zt, q1in, upd, rst, whz);
        gru_stage2_kernel<<<dim3(4, 4), 256>>>(in[22], q1in, rst, upd, whz, q1out);

        if (t == TT - 1) {
            // final output: relu(A[7] @ (h1 @ Qn1))
            sgemm_kernel<<<dim3(4, 32), 256>>>(h1, q1out, Y, NN, F, F, 0);
            sgemm_kernel<<<dim3(4, 32), 256>>>(At, Y, (float*)d_out, NN, F, NN, 1);
        }
    }
}